// round 12
// baseline (speedup 1.0000x reference)
#include <cuda_runtime.h>
#include <math.h>

#define NPIX 256
#define NFFT 512
#define KBW  6            // ES kernel width (fine-grid cells)
#define KBHALF 3
#define KBBETA (2.30f * KBW)
#define MUOFF 132         // fft_cols covers mu_signed in [-132, 131]
#define NMU   264

// Scratch (__device__ globals; no allocations)
__device__ float d_invd[NPIX];                           // 1/psi((x-128)/512)
__device__ __align__(16) float2 d_R[NPIX * NFFT];        // row FFTs: R[y][mu]
__device__ __align__(16) float2 d_F[NFFT * NFFT];        // spectrum, TRANSPOSED: F[mu][mv]

// ---------- ES spreading kernel ----------
__device__ __forceinline__ float es_phi(float z) {
    float t = 1.f - z * z * (1.f / (KBHALF * KBHALF));
    return expf(KBBETA * (sqrtf(fmaxf(t, 0.f)) - 1.f));
}

// ---------- Kernel A: deapodization table (1 block per x) ----------
__global__ void __launch_bounds__(128) dpd_kernel() {
    __shared__ float red[128];
    const int x = blockIdx.x;
    const int tid = threadIdx.x;
    const float xi = (float)(x - NPIX / 2) / (float)NFFT;
    const int NQ = 128;
    const float h = (2.f * KBHALF) / NQ;
    float s = 0.f;
    for (int i = tid; i <= NQ; i += 128) {
        float z = -KBHALF + h * i;
        float c = cospif(2.f * xi * z);
        float wgt = (i == 0 || i == NQ) ? 0.5f : 1.f;
        s += wgt * es_phi(z) * c;
    }
    red[tid] = s;
    __syncthreads();
    for (int d = 64; d > 0; d >>= 1) {
        if (tid < d) red[tid] += red[tid + d];
        __syncthreads();
    }
    if (tid == 0) d_invd[x] = 1.f / (red[0] * h);
}

// ---------- Stockham radix-2 512-pt FFT, twiddles from smem table ----------
// tw[m] = exp(-i*pi*m/256), m=0..255. Result ends in bufB.
__device__ __forceinline__ void fft512(float2* bufA, float2* bufB,
                                       const float2* tw, int tid) {
    float2 *src = bufA, *dst = bufB;
#pragma unroll
    for (int s = 0; s < 9; ++s) {
        const int L = 1 << s;
        __syncthreads();
        int kk = tid & (L - 1);
        float2 w = tw[kk << (8 - s)];
        float2 a = src[tid], b = src[tid + 256];
        float tbr = b.x * w.x - b.y * w.y;
        float tbi = b.x * w.y + b.y * w.x;
        dst[2 * tid - kk]     = make_float2(a.x + tbr, a.y + tbi);
        dst[2 * tid - kk + L] = make_float2(a.x - tbr, a.y - tbi);
        float2* tmp = src; src = dst; dst = tmp;
    }
    __syncthreads();
}

// ---------- Kernel B: fused softplus + Hann conv + deapodize + row FFT ----------
__global__ void __launch_bounds__(256) fft_rows_kernel(const float* __restrict__ base) {
    __shared__ float2 bufA[NFFT], bufB[NFFT];
    __shared__ float2 tw[256];
    __shared__ float sp[3][NPIX];
    const int y = blockIdx.x;
    const int tid = threadIdx.x;

    float twr, twi; sincospif(-(float)tid / 256.f, &twi, &twr);
    tw[tid] = make_float2(twr, twi);

#pragma unroll
    for (int d = 0; d < 3; ++d) {
        int yy = y - 1 + d;
        float v = 0.f;
        if (yy >= 0 && yy < NPIX) {
            float b = base[yy * NPIX + tid];
            v = fmaxf(b, 0.f) + log1pf(expf(-fabsf(b)));
        }
        sp[d][tid] = v;
    }
    __syncthreads();

    float acc = 0.f;
    {
        const float hy[3] = {0.25f, 0.5f, 0.25f};
#pragma unroll
        for (int d = 0; d < 3; ++d) {
            float l = (tid > 0)        ? sp[d][tid - 1] : 0.f;
            float m = sp[d][tid];
            float r = (tid < NPIX - 1) ? sp[d][tid + 1] : 0.f;
            acc += hy[d] * (0.25f * l + 0.5f * m + 0.25f * r);
        }
    }
    float val = acc * d_invd[y] * d_invd[tid];

    int j = (tid >= 128) ? (tid - 128) : (tid + 384);
    bufA[128 + tid] = make_float2(0.f, 0.f);
    __syncthreads();
    bufA[j] = make_float2(val, 0.f);

    fft512(bufA, bufB, tw, tid);
    d_R[y * NFFT + tid]       = bufB[tid];
    d_R[y * NFFT + tid + 256] = bufB[tid + 256];
}

// ---------- Kernel C: column FFTs, only needed mu; TRANSPOSED coalesced store ----------
__global__ void __launch_bounds__(256) fft_cols_kernel() {
    __shared__ float2 bufA[NFFT], bufB[NFFT];
    __shared__ float2 tw[256];
    const int tid = threadIdx.x;
    const int mu = (blockIdx.x - MUOFF) & (NFFT - 1);

    float twr, twi; sincospif(-(float)tid / 256.f, &twi, &twr);
    tw[tid] = make_float2(twr, twi);

    int j = (tid >= 128) ? (tid - 128) : (tid + 384);
    bufA[128 + tid] = make_float2(0.f, 0.f);
    __syncthreads();
    bufA[j] = d_R[tid * NFFT + mu];

    fft512(bufA, bufB, tw, tid);
    d_F[mu * NFFT + tid]       = bufB[tid];
    d_F[mu * NFFT + tid + 256] = bufB[tid + 256];
}

// ---------- Kernel D: one-warp-per-visibility 6x6 interpolation ----------
// Tap i (i=0..35): tu=i/6, tv=i%6. Lane i handles tap i (i<32); lanes 0-3 also
// handle taps 32-35. All 36 taps of a vis live in 6 rows x 48B -> ~6-12 L1 lines
// per vis instead of ~36 (the R11 bottleneck). Full-warp shfl reduction.
__global__ void __launch_bounds__(256) interp_kernel(const float* __restrict__ uu,
                              const float* __restrict__ vv,
                              float* __restrict__ out, int nvis, int mode) {
    const int lane = threadIdx.x & 31;
    const int k = blockIdx.x * 8 + (threadIdx.x >> 5);   // 8 warps/CTA, 1 vis/warp
    if (k >= nvis) return;

    const float ARCSEC_F = (float)(M_PI / 180.0 / 3600.0);
    const float cell_rad = 0.005f * ARCSEC_F;
    const float fu = (uu[k] * 1e3f) * cell_rad;          // |fu| <= 0.25
    const float fv = (vv[k] * 1e3f) * cell_rad;
    const float gu = (float)NFFT * fu;
    const float gv = (float)NFFT * fv;
    const int bu = (int)floorf(gu);
    const int bv = (int)floorf(gv);

    float vr = 0.f, vi = 0.f;
#pragma unroll
    for (int pass = 0; pass < 2; ++pass) {
        int i = lane + pass * 32;
        if (i < KBW * KBW) {
            int tu = i / KBW, tv = i - tu * KBW;
            float wu = es_phi(gu - (float)(bu - 2 + tu));
            float wv = es_phi(gv - (float)(bv - 2 + tv));
            int mu = (bu - 2 + tu) & (NFFT - 1);
            int mv = (bv - 2 + tv) & (NFFT - 1);
            float2 f = __ldg(&d_F[mu * NFFT + mv]);
            float w = wu * wv;
            vr += w * f.x;
            vi += w * f.y;
        }
    }

    // full-warp reduction
#pragma unroll
    for (int off = 16; off > 0; off >>= 1) {
        vr += __shfl_down_sync(0xffffffffu, vr, off);
        vi += __shfl_down_sync(0xffffffffu, vi, off);
    }

    if (lane == 0) {
        float c2 = cell_rad * cell_rad;
        float orr = vr * c2;
        float oii = vi * c2;
        if (mode == 0) {
            out[k] = orr;
        } else {
            out[2 * k + 0] = orr;
            out[2 * k + 1] = oii;
        }
    }
}

extern "C" void kernel_launch(void* const* d_in, const int* in_sizes, int n_in,
                              void* d_out, int out_size) {
    // Input mapping by size (proven R4-R11): image is the 65536-element input;
    // the remaining two, in order, are uu then vv.
    int img_i = -1;
    for (int i = 0; i < n_in; ++i)
        if (in_sizes[i] == NPIX * NPIX) { img_i = i; break; }
    if (img_i < 0) img_i = 0;
    int uv_idx[2]; int c = 0;
    for (int i = 0; i < n_in && c < 2; ++i)
        if (i != img_i) uv_idx[c++] = i;

    const float* base = (const float*)d_in[img_i];
    const float* uu   = (const float*)d_in[uv_idx[0]];
    const float* vv   = (const float*)d_in[uv_idx[1]];
    float* out = (float*)d_out;
    const int nvis = in_sizes[uv_idx[0]];

    // Output-mode logic (proven R4-R11).
    int mode = (out_size >= 2 * nvis) ? 1 : 0;

    dpd_kernel<<<NPIX, 128>>>();
    fft_rows_kernel<<<NPIX, 256>>>(base);
    fft_cols_kernel<<<NMU, 256>>>();
    interp_kernel<<<(nvis + 7) / 8, 256>>>(uu, vv, out, nvis, mode);
}